// round 17
// baseline (speedup 1.0000x reference)
#include <cuda_runtime.h>
#include <math.h>

#define BB 64
#define SS 512
#define HH 768
#define LL 9
#define NTOK (BB*SS)
#define TPW 8              // tokens per warp
#define WPB 4              // warps per block (128 threads)
#define TOKPB (TPW*WPB)    // 32 tokens per block (one row spans 16 blocks)
#define WPAD 12            // padded W row stride (floats): conflict-free + float4-able

typedef unsigned long long u64;

__device__ __forceinline__ u64 pack2(float lo, float hi) {
    u64 r; asm("mov.b64 %0, {%1, %2};" : "=l"(r) : "f"(lo), "f"(hi)); return r;
}
__device__ __forceinline__ void unpack2(u64 v, float &lo, float &hi) {
    asm("mov.b64 {%0, %1}, %2;" : "=f"(lo), "=f"(hi) : "l"(v));
}
__device__ __forceinline__ void ffma2(u64 &d, u64 a, u64 b) {
    asm("fma.rn.f32x2 %0, %1, %2, %0;" : "+l"(d) : "l"(a), "l"(b));
}
__device__ __forceinline__ u64 fadd2(u64 a, u64 b) {
    u64 r; asm("add.rn.f32x2 %0, %1, %2;" : "=l"(r) : "l"(a), "l"(b)); return r;
}

// ---------------------------------------------------------------------------
// Champion kernel (32.9us = R2 + unroll 8), single change this round:
// __launch_bounds__ occupancy hint 4 -> 3 blocks/SM. R15 showed regs pinned
// at exactly 128 (the 4-block cap) -- ptxas's software-pipeliner was register-
// clipped mid-hoist. Raising the budget to ~168 regs lets it pipeline the
// full unroll-8 load window; per-warp MLP (the confirmed binding variable)
// rises, at the cost of 16 -> 12 warps/SM (shown non-binding in R4/R14).
//   1. per-block re-scan of this row's valid_mask -> slot code per token
//   2. tall-skinny GEMM [8 tok/warp, 768] @ [768, 9], token-pair f32x2 FMAs
//   3. bias + softmax + compacting scatter (bijection; no pre-fill needed)
// ---------------------------------------------------------------------------
__global__ __launch_bounds__(128, 3) void bertner_kernel(
    const float* __restrict__ X, const int* __restrict__ mask,
    const float* __restrict__ W, const float* __restrict__ bias,
    float* __restrict__ out) {

    __shared__ float shW[HH * WPAD];
    __shared__ int   sh_slot[TOKPB];
    __shared__ int   sh_wsum[WPB];

    int tid  = threadIdx.x;
    int lane = tid & 31;
    int wid  = tid >> 5;

    // ---- cooperative W load into padded smem ----
    for (int idx = tid; idx < HH * LL; idx += 128) {
        int k = idx / LL;
        int j = idx - k * LL;
        shW[k * WPAD + j] = W[idx];
    }

    // ---- per-row compaction scan (each block redundantly scans its row) ----
    int tokblk = blockIdx.x * TOKPB;
    int row    = tokblk >> 9;          // / SS
    int r0     = tokblk & (SS - 1);    // row-local start of this block's tokens

    int4 m4 = ((const int4*)(mask + row * SS))[tid];   // tokens 4*tid .. 4*tid+3
    int msum = m4.x + m4.y + m4.z + m4.w;
    int v = msum;
    #pragma unroll
    for (int o = 1; o < 32; o <<= 1) {
        int n = __shfl_up_sync(0xffffffffu, v, o);
        if (lane >= o) v += n;
    }
    if (lane == 31) sh_wsum[wid] = v;
    __syncthreads();

    int wpre = 0;
    #pragma unroll
    for (int w = 0; w < WPB; w++) if (w < wid) wpre += sh_wsum[w];
    int total = sh_wsum[0] + sh_wsum[1] + sh_wsum[2] + sh_wsum[3];
    int run = wpre + v - msum;         // exclusive valid-prefix before token 4*tid

    int mm[4] = {m4.x, m4.y, m4.z, m4.w};
    #pragma unroll
    for (int c = 0; c < 4; c++) {
        int sc = 4 * tid + c;
        int code;
        if (mm[c]) { code = run; run++; }
        else       { code = ~(total + sc - run); }   // tail slot, encoded negative
        if (sc >= r0 && sc < r0 + TOKPB) sh_slot[sc - r0] = code;
    }
    __syncthreads();   // covers shW + sh_slot

    // ---- main GEMM: warp handles 8 tokens, lane owns k = lane + 32*i ----
    int tok0 = tokblk + wid * TPW;
    const float* xb = X + (size_t)tok0 * HH;

    u64 acc[TPW/2][LL];
    #pragma unroll
    for (int p = 0; p < TPW/2; p++)
        #pragma unroll
        for (int j = 0; j < LL; j++) acc[p][j] = 0ull;

    const float4* shW4 = (const float4*)shW;

    #pragma unroll 8
    for (int i = 0; i < HH / 32; i++) {       // 24 iterations
        int k = i * 32 + lane;
        float4 w0 = shW4[k * 3 + 0];
        float4 w1 = shW4[k * 3 + 1];
        float4 w2 = shW4[k * 3 + 2];
        float xv[TPW];
        #pragma unroll
        for (int t = 0; t < TPW; t++) xv[t] = xb[t * HH + k];
        u64 xp[TPW/2];
        #pragma unroll
        for (int p = 0; p < TPW/2; p++) xp[p] = pack2(xv[2*p], xv[2*p+1]);

        float wv[LL] = {w0.x, w0.y, w0.z, w0.w, w1.x, w1.y, w1.z, w1.w, w2.x};
        #pragma unroll
        for (int j = 0; j < LL; j++) {
            u64 wp = pack2(wv[j], wv[j]);
            #pragma unroll
            for (int p = 0; p < TPW/2; p++) ffma2(acc[p][j], xp[p], wp);
        }
    }

    // ---- packed butterfly reduction: every lane ends with full sums ----
    #pragma unroll
    for (int p = 0; p < TPW/2; p++)
        #pragma unroll
        for (int j = 0; j < LL; j++)
            #pragma unroll
            for (int o = 16; o > 0; o >>= 1) {
                u64 other = __shfl_xor_sync(0xffffffffu, acc[p][j], o);
                acc[p][j] = fadd2(acc[p][j], other);
            }

    // ---- bias + bias-softmax precompute (cheap, per thread) ----
    float bb[LL], be[LL];
    #pragma unroll
    for (int j = 0; j < LL; j++) bb[j] = bias[j];
    float bmx = bb[0];
    #pragma unroll
    for (int j = 1; j < LL; j++) bmx = fmaxf(bmx, bb[j]);
    float bsum = 0.f;
    #pragma unroll
    for (int j = 0; j < LL; j++) { be[j] = expf(bb[j] - bmx); bsum += be[j]; }
    float binv = 1.f / bsum;

    // ---- finalize: lanes 0..7 each own one token (static acc indexing) ----
    #pragma unroll
    for (int t = 0; t < TPW; t++) {
        if (lane == t) {
            int code = sh_slot[wid * TPW + t];
            if (code >= 0) {
                float v2[LL];
                float mx = -1e30f;
                #pragma unroll
                for (int j = 0; j < LL; j++) {
                    float lo, hi;
                    unpack2(acc[t >> 1][j], lo, hi);
                    v2[j] = ((t & 1) ? hi : lo) + bb[j];
                    mx = fmaxf(mx, v2[j]);
                }
                float ssum = 0.f;
                #pragma unroll
                for (int j = 0; j < LL; j++) { v2[j] = expf(v2[j] - mx); ssum += v2[j]; }
                float inv = 1.f / ssum;
                float* o = out + ((size_t)row * SS + code) * LL;
                #pragma unroll
                for (int j = 0; j < LL; j++) o[j] = v2[j] * inv;
            } else {
                int islot = ~code;
                float* o = out + ((size_t)row * SS + islot) * LL;
                #pragma unroll
                for (int j = 0; j < LL; j++) o[j] = be[j] * binv;
            }
        }
    }
}

// ---------------------------------------------------------------------------
// Launch. Inputs (metadata order): sequence_output f32[64*512*768],
// valid_mask i32[64*512], W f32[768*9], b f32[9]. Output f32[64*512*9].
// ---------------------------------------------------------------------------
extern "C" void kernel_launch(void* const* d_in, const int* in_sizes, int n_in,
                              void* d_out, int out_size) {
    const float* X    = (const float*)d_in[0];
    const int*   mask = (const int*)d_in[1];
    const float* W    = (const float*)d_in[2];
    const float* bias = (const float*)d_in[3];
    float* out = (float*)d_out;

    bertner_kernel<<<NTOK / TOKPB, 128>>>(X, mask, W, bias, out);
}